// round 8
// baseline (speedup 1.0000x reference)
#include <cuda_runtime.h>
#include <cuda_bf16.h>
#include <math.h>
#include <stdint.h>

#define D_MODEL   1024
#define D_STATE   16
#define D_CONV    4
#define D_INNER   2048
#define DT_RANK   64
#define IN_SIZE   512
#define OUT_SIZE  512
#define BATCH     2048
#define XDB_COLS  96
#define STATE_W   20

typedef __nv_bfloat16 bf16;

// ---------------- fp32 scratch ----------------
__device__ float g_xc[BATCH * D_INNER];
__device__ float g_gz[BATCH * D_INNER];          // silu(z)
__device__ float g_xdb[BATCH * XDB_COLS];
__device__ float g_bz[2 * D_INNER];
// ---------------- bf16 split scratch ----------------
__device__ bf16 g_x_hi[BATCH * IN_SIZE],   g_x_lo[BATCH * IN_SIZE];
__device__ bf16 g_xc_hi[BATCH * D_INNER],  g_xc_lo[BATCH * D_INNER];
__device__ bf16 g_y_hi[BATCH * D_INNER],   g_y_lo[BATCH * D_INNER];
__device__ bf16 g_wi_hi[IN_SIZE * D_MODEL],     g_wi_lo[IN_SIZE * D_MODEL];
__device__ bf16 g_ip_hi[2 * D_INNER * D_MODEL], g_ip_lo[2 * D_INNER * D_MODEL];
__device__ bf16 g_wxz_hi[2 * D_INNER * IN_SIZE], g_wxz_lo[2 * D_INNER * IN_SIZE];
__device__ bf16 g_w4_hi[XDB_COLS * D_INNER],    g_w4_lo[XDB_COLS * D_INNER];
__device__ bf16 g_w5_hi[D_INNER * DT_RANK],     g_w5_lo[D_INNER * DT_RANK];
__device__ bf16 g_opT_hi[D_INNER * D_MODEL],    g_opT_lo[D_INNER * D_MODEL];
__device__ bf16 g_woT_hi[OUT_SIZE * D_MODEL],   g_woT_lo[OUT_SIZE * D_MODEL];
__device__ bf16 g_wf_hi[OUT_SIZE * D_INNER],    g_wf_lo[OUT_SIZE * D_INNER];

// ---------------- helpers ----------------
__device__ __forceinline__ float softplusf(float x) {
    return (x > 0.f) ? (x + log1pf(__expf(-x))) : log1pf(__expf(x));
}
__device__ __forceinline__ float siluf(float x) {
    return x / (1.f + __expf(-x));
}
__device__ __forceinline__ void bsplit(float v, bf16& h, bf16& l) {
    h = __float2bfloat16_rn(v);
    l = __float2bfloat16_rn(v - __bfloat162float(h));
}
__device__ __forceinline__ uint32_t packbf(float a, float b) {
    __nv_bfloat162 p = {__float2bfloat16_rn(a), __float2bfloat16_rn(b)};
    return *(uint32_t*)&p;
}
__device__ __forceinline__ void mmabf(float* c, const uint32_t* a, const uint32_t* b) {
    asm volatile(
        "mma.sync.aligned.m16n8k16.row.col.f32.bf16.bf16.f32 "
        "{%0,%1,%2,%3}, {%4,%5,%6,%7}, {%8,%9}, {%0,%1,%2,%3};"
        : "+f"(c[0]), "+f"(c[1]), "+f"(c[2]), "+f"(c[3])
        : "r"(a[0]), "r"(a[1]), "r"(a[2]), "r"(a[3]), "r"(b[0]), "r"(b[1]));
}
__device__ __forceinline__ void cpa16(uint32_t dst, const void* src, bool p) {
    int sz = p ? 16 : 0;
    asm volatile("cp.async.cg.shared.global [%0], [%1], 16, %2;\n"
                 :: "r"(dst), "l"(src), "r"(sz));
}

// ======================================================================
// 2xBF16-split tensor GEMM. C[M,N] = A[M,K] @ B[N,K]^T.
// BM=BN=128, BK=64 elem, 256 thr, warps 4(m)x2(n), warp tile 32x64.
// EPI: 0 none, 1 +bias, 3 fused mamba conv/z epilogue.
// ======================================================================
#define TG_SMEM (2 * 4 * 128 * 36 * 4)   // 147456 B

template<int EPI, bool SPLITK, bool WSPLIT>
__global__ void __launch_bounds__(256, 1)
bgemm(const bf16* __restrict__ Ahi, const bf16* __restrict__ Alo,
      const bf16* __restrict__ Bhi, const bf16* __restrict__ Blo,
      float* __restrict__ C, bf16* __restrict__ Chi, bf16* __restrict__ Clo,
      const float* __restrict__ bias,
      int M, int N, int K, int lda, int ldb, int ldc,
      const float* __restrict__ rnn, const float* __restrict__ cw,
      const float* __restrict__ cb, float* __restrict__ ost,
      float* __restrict__ xc, bf16* __restrict__ xch, bf16* __restrict__ xcl,
      float* __restrict__ gz)
{
    extern __shared__ uint32_t smbuf[];
    constexpr int TSZ = 128 * 36;
    constexpr int STAGE = 4 * TSZ;

    const uint32_t* A32h = reinterpret_cast<const uint32_t*>(Ahi);
    const uint32_t* A32l = reinterpret_cast<const uint32_t*>(Alo);
    const uint32_t* B32h = reinterpret_cast<const uint32_t*>(Bhi);
    const uint32_t* B32l = reinterpret_cast<const uint32_t*>(Blo);
    const int ldap = lda >> 1, ldbp = ldb >> 1;

    const int tid  = threadIdx.x;
    const int lane = tid & 31;
    const int warp = tid >> 5;
    const int wm   = warp & 3;
    const int wn   = warp >> 2;
    const int m0   = blockIdx.y * 128;
    const int n0   = blockIdx.x * 128;
    const int Kc   = SPLITK ? (K / gridDim.z) : K;
    const int k0b  = SPLITK ? (blockIdx.z * Kc) : 0;
    const int T    = Kc / 64;

    const int lr = tid >> 3;
    const int lc = (tid & 7) * 4;

    float acc[2][8][4];
#pragma unroll
    for (int i = 0; i < 2; i++)
#pragma unroll
        for (int j = 0; j < 8; j++)
#pragma unroll
            for (int q = 0; q < 4; q++) acc[i][j][q] = 0.f;

    auto fill = [&](int t, int st) {
        uint32_t* Ah = smbuf + st * STAGE;
        uint32_t* Al = Ah + TSZ;
        uint32_t* Bh = Al + TSZ;
        uint32_t* Bl = Bh + TSZ;
        const int kp0 = (k0b + t * 64) >> 1;
#pragma unroll
        for (int it = 0; it < 4; it++) {
            const int row = lr + it * 32;
            const size_t g = (size_t)(m0 + row) * ldap + kp0 + lc;
            cpa16((uint32_t)__cvta_generic_to_shared(&Ah[row * 36 + lc]), A32h + g, true);
            cpa16((uint32_t)__cvta_generic_to_shared(&Al[row * 36 + lc]), A32l + g, true);
        }
#pragma unroll
        for (int it = 0; it < 4; it++) {
            const int row = lr + it * 32;
            const bool p = SPLITK ? ((n0 + row) < N) : true;
            const size_t g = (size_t)(n0 + row) * ldbp + kp0 + lc;
            cpa16((uint32_t)__cvta_generic_to_shared(&Bh[row * 36 + lc]), B32h + g, p);
            cpa16((uint32_t)__cvta_generic_to_shared(&Bl[row * 36 + lc]), B32l + g, p);
        }
    };

    auto compute = [&](int st) {
        uint32_t* Ah = smbuf + st * STAGE;
        uint32_t* Al = Ah + TSZ;
        uint32_t* Bh = Al + TSZ;
        uint32_t* Bl = Bh + TSZ;
#pragma unroll
        for (int ks = 0; ks < 32; ks += 8) {
            uint32_t ah[2][4], al[2][4];
#pragma unroll
            for (int mt = 0; mt < 2; mt++) {
                const int mr = wm * 32 + mt * 16 + (lane >> 2);
                const int kc = ks + (lane & 3);
                ah[mt][0] = Ah[mr * 36 + kc];
                ah[mt][1] = Ah[(mr + 8) * 36 + kc];
                ah[mt][2] = Ah[mr * 36 + kc + 4];
                ah[mt][3] = Ah[(mr + 8) * 36 + kc + 4];
                al[mt][0] = Al[mr * 36 + kc];
                al[mt][1] = Al[(mr + 8) * 36 + kc];
                al[mt][2] = Al[mr * 36 + kc + 4];
                al[mt][3] = Al[(mr + 8) * 36 + kc + 4];
            }
            uint32_t bh[8][2], bl[8][2];
#pragma unroll
            for (int nt = 0; nt < 8; nt++) {
                const int nc = wn * 64 + nt * 8 + (lane >> 2);
                const int kc = ks + (lane & 3);
                bh[nt][0] = Bh[nc * 36 + kc];
                bh[nt][1] = Bh[nc * 36 + kc + 4];
                bl[nt][0] = Bl[nc * 36 + kc];
                bl[nt][1] = Bl[nc * 36 + kc + 4];
            }
#pragma unroll
            for (int mt = 0; mt < 2; mt++)
#pragma unroll
                for (int nt = 0; nt < 8; nt++) {
                    mmabf(acc[mt][nt], ah[mt], bl[nt]);
                    mmabf(acc[mt][nt], al[mt], bh[nt]);
                    mmabf(acc[mt][nt], ah[mt], bh[nt]);
                }
        }
    };

    fill(0, 0);
    asm volatile("cp.async.commit_group;" ::: "memory");
    for (int t = 0; t < T; t++) {
        if (t + 1 < T) {
            fill(t + 1, (t + 1) & 1);
            asm volatile("cp.async.commit_group;" ::: "memory");
            asm volatile("cp.async.wait_group 1;" ::: "memory");
        } else {
            asm volatile("cp.async.wait_group 0;" ::: "memory");
        }
        __syncthreads();
        compute(t & 1);
        __syncthreads();
    }

    // ---- epilogue
    const bool convBlock = (EPI == 3) && (n0 < D_INNER);
#pragma unroll
    for (int mt = 0; mt < 2; mt++) {
        const int mrb = m0 + wm * 32 + mt * 16 + (lane >> 2);
#pragma unroll
        for (int nt = 0; nt < 8; nt++) {
            const int nc = n0 + wn * 64 + nt * 8 + (lane & 3) * 2;
            float v0 = acc[mt][nt][0], v1 = acc[mt][nt][1];
            float v2 = acc[mt][nt][2], v3 = acc[mt][nt][3];
            if (SPLITK) {
                if (nc < N) {
                    atomicAdd(&C[(size_t)mrb * ldc + nc], v0);
                    atomicAdd(&C[(size_t)mrb * ldc + nc + 1], v1);
                    atomicAdd(&C[(size_t)(mrb + 8) * ldc + nc], v2);
                    atomicAdd(&C[(size_t)(mrb + 8) * ldc + nc + 1], v3);
                }
                continue;
            }
            if (EPI >= 1) {
                const float b0 = bias[nc], b1 = bias[nc + 1];
                v0 += b0; v1 += b1; v2 += b0; v3 += b1;
            }
            if (EPI == 3) {
                float vv[4] = {v0, v1, v2, v3};
#pragma unroll
                for (int e = 0; e < 4; e++) {
                    const int b = mrb + (e >> 1) * 8;
                    const int d = nc + (e & 1) - (convBlock ? 0 : D_INNER);
                    if (convBlock) {
                        const size_t srow = (size_t)b * (D_INNER * STATE_W) + (size_t)d * STATE_W;
                        float4 cs = *reinterpret_cast<const float4*>(rnn + srow);
                        float4 w  = *reinterpret_cast<const float4*>(cw + d * 4);
                        float c = cs.y * w.x + cs.z * w.y + cs.w * w.z + vv[e] * w.w + cb[d];
                        float s = siluf(c);
                        const size_t bd = (size_t)b * D_INNER + d;
                        xc[bd] = s;
                        bf16 h, l; bsplit(s, h, l);
                        xch[bd] = h; xcl[bd] = l;
                        *reinterpret_cast<float4*>(ost + srow) = make_float4(cs.y, cs.z, cs.w, vv[e]);
                    } else {
                        gz[(size_t)b * D_INNER + d] = siluf(vv[e]);
                    }
                }
                continue;
            }
            if (WSPLIT) {
                bf16 h0, l0, h1, l1, h2, l2, h3, l3;
                bsplit(v0, h0, l0); bsplit(v1, h1, l1);
                bsplit(v2, h2, l2); bsplit(v3, h3, l3);
                __nv_bfloat162 ha = {h0, h1}, hb = {h2, h3};
                __nv_bfloat162 la = {l0, l1}, lb = {l2, l3};
                *reinterpret_cast<uint32_t*>(&Chi[(size_t)mrb * ldc + nc])       = *(uint32_t*)&ha;
                *reinterpret_cast<uint32_t*>(&Chi[(size_t)(mrb + 8) * ldc + nc]) = *(uint32_t*)&hb;
                *reinterpret_cast<uint32_t*>(&Clo[(size_t)mrb * ldc + nc])       = *(uint32_t*)&la;
                *reinterpret_cast<uint32_t*>(&Clo[(size_t)(mrb + 8) * ldc + nc]) = *(uint32_t*)&lb;
            } else {
                *reinterpret_cast<float2*>(&C[(size_t)mrb * ldc + nc])       = make_float2(v0, v1);
                *reinterpret_cast<float2*>(&C[(size_t)(mrb + 8) * ldc + nc]) = make_float2(v2, v3);
            }
        }
    }
}

// ======================================================================
// Fused dt-GEMM + SSM update. dt = softplus(xdb[:, :64] @ w5^T + dtb),
// then full state update + y gating. K=64 (single chunk).
// ======================================================================
#define DS_TSZ   (128 * 36)
#define DS_EXPA  (4 * DS_TSZ)              // u32 offset of expA (2048 f)
#define DS_BC    (DS_EXPA + 2048)          // u32 offset of BC (4096 f)
#define DS_SMEM  ((DS_BC + 4096) * 4)      // 98304 B

__global__ void __launch_bounds__(256, 1)
dtssm_kernel(const float* __restrict__ xdb,
             const bf16* __restrict__ w5H, const bf16* __restrict__ w5L,
             const float* __restrict__ dtb, const float* __restrict__ A_log,
             const float* __restrict__ Dp, const float* __restrict__ xc_,
             const float* __restrict__ gz_, const float* __restrict__ rnn,
             float* __restrict__ ost, bf16* __restrict__ yh, bf16* __restrict__ yl)
{
    extern __shared__ uint32_t smbuf[];
    uint32_t* Ah = smbuf;
    uint32_t* Al = Ah + DS_TSZ;
    uint32_t* Bh = Al + DS_TSZ;
    uint32_t* Bl = Bh + DS_TSZ;
    float* expA = reinterpret_cast<float*>(smbuf + DS_EXPA);
    float* BC   = reinterpret_cast<float*>(smbuf + DS_BC);

    const int tid  = threadIdx.x;
    const int lane = tid & 31;
    const int warp = tid >> 5;
    const int wm   = warp & 3;
    const int wn   = warp >> 2;
    const int m0   = blockIdx.y * 128;    // batch
    const int n0   = blockIdx.x * 128;    // d_inner

    // ---- B tile via cp.async (w5: [2048 x 64] bf16 -> 32 u32/row)
    {
        const int lr = tid >> 3, lc = (tid & 7) * 4;
        const uint32_t* B32h = reinterpret_cast<const uint32_t*>(w5H);
        const uint32_t* B32l = reinterpret_cast<const uint32_t*>(w5L);
#pragma unroll
        for (int it = 0; it < 4; it++) {
            const int row = lr + it * 32;
            const size_t g = (size_t)(n0 + row) * 32 + lc;
            cpa16((uint32_t)__cvta_generic_to_shared(&Bh[row * 36 + lc]), B32h + g, true);
            cpa16((uint32_t)__cvta_generic_to_shared(&Bl[row * 36 + lc]), B32l + g, true);
        }
        asm volatile("cp.async.commit_group;" ::: "memory");
    }
    // ---- A tile: xdb fp32 [rows m0.., cols 0..63] -> split to smem
#pragma unroll
    for (int it = 0; it < 8; it++) {
        const int idx = it * 256 + tid;        // 0..2047
        const int row = idx >> 4;
        const int c4  = (idx & 15) * 4;        // col 0..60
        float4 v = *reinterpret_cast<const float4*>(&xdb[(size_t)(m0 + row) * XDB_COLS + c4]);
        bf16 h0, l0, h1, l1, h2, l2, h3, l3;
        bsplit(v.x, h0, l0); bsplit(v.y, h1, l1);
        bsplit(v.z, h2, l2); bsplit(v.w, h3, l3);
        __nv_bfloat162 hp0 = {h0, h1}, hp1 = {h2, h3};
        __nv_bfloat162 lp0 = {l0, l1}, lp1 = {l2, l3};
        const int pc = (idx & 15) * 2;
        Ah[row * 36 + pc]     = *(uint32_t*)&hp0;
        Ah[row * 36 + pc + 1] = *(uint32_t*)&hp1;
        Al[row * 36 + pc]     = *(uint32_t*)&lp0;
        Al[row * 36 + pc + 1] = *(uint32_t*)&lp1;
    }
    // ---- expA table: exp(A_log) for d in [n0, n0+128)
#pragma unroll
    for (int it = 0; it < 8; it++) {
        const int i = it * 256 + tid;          // 0..2047
        expA[i] = __expf(A_log[(size_t)(n0 + (i >> 4)) * D_STATE + (i & 15)]);
    }
    // ---- BC: Bm,Cm for batch rows [m0, m0+128): BC[row*32 + c] = xdb[row, 64+c]
#pragma unroll
    for (int it = 0; it < 4; it++) {
        const int i = it * 256 + tid;          // 0..1023 f4 units
        const int row = i >> 3;
        const int c4 = (i & 7) * 4;
        float4 v = *reinterpret_cast<const float4*>(&xdb[(size_t)(m0 + row) * XDB_COLS + DT_RANK + c4]);
        *reinterpret_cast<float4*>(&BC[row * 32 + c4]) = v;
    }
    asm volatile("cp.async.wait_group 0;" ::: "memory");
    __syncthreads();

    // ---- single-chunk compute (K=64)
    float acc[2][8][4];
#pragma unroll
    for (int i = 0; i < 2; i++)
#pragma unroll
        for (int j = 0; j < 8; j++)
#pragma unroll
            for (int q = 0; q < 4; q++) acc[i][j][q] = 0.f;
#pragma unroll
    for (int ks = 0; ks < 32; ks += 8) {
        uint32_t ah[2][4], al[2][4];
#pragma unroll
        for (int mt = 0; mt < 2; mt++) {
            const int mr = wm * 32 + mt * 16 + (lane >> 2);
            const int kc = ks + (lane & 3);
            ah[mt][0] = Ah[mr * 36 + kc];
            ah[mt][1] = Ah[(mr + 8) * 36 + kc];
            ah[mt][2] = Ah[mr * 36 + kc + 4];
            ah[mt][3] = Ah[(mr + 8) * 36 + kc + 4];
            al[mt][0] = Al[mr * 36 + kc];
            al[mt][1] = Al[(mr + 8) * 36 + kc];
            al[mt][2] = Al[mr * 36 + kc + 4];
            al[mt][3] = Al[(mr + 8) * 36 + kc + 4];
        }
        uint32_t bh[8][2], bl[8][2];
#pragma unroll
        for (int nt = 0; nt < 8; nt++) {
            const int nc = wn * 64 + nt * 8 + (lane >> 2);
            const int kc = ks + (lane & 3);
            bh[nt][0] = Bh[nc * 36 + kc];
            bh[nt][1] = Bh[nc * 36 + kc + 4];
            bl[nt][0] = Bl[nc * 36 + kc];
            bl[nt][1] = Bl[nc * 36 + kc + 4];
        }
#pragma unroll
        for (int mt = 0; mt < 2; mt++)
#pragma unroll
            for (int nt = 0; nt < 8; nt++) {
                mmabf(acc[mt][nt], ah[mt], bl[nt]);
                mmabf(acc[mt][nt], al[mt], bh[nt]);
                mmabf(acc[mt][nt], ah[mt], bh[nt]);
            }
    }

    // ---- fused SSM epilogue
#pragma unroll
    for (int mt = 0; mt < 2; mt++) {
        const int mrb = m0 + wm * 32 + mt * 16 + (lane >> 2);
#pragma unroll
        for (int nt = 0; nt < 8; nt++) {
            const int nc = n0 + wn * 64 + nt * 8 + (lane & 3) * 2;
            float yo[4];
#pragma unroll
            for (int e = 0; e < 4; e++) {
                const int b = mrb + (e >> 1) * 8;
                const int d = nc + (e & 1);
                const int lb = b - m0, ld = d - n0;
                const float dt = softplusf(acc[mt][nt][e] + dtb[d]);
                const size_t bd = (size_t)b * D_INNER + d;
                const float xcv = xc_[bd];
                const float dtxc = dt * xcv;
                const float* eA = &expA[ld * 16];
                const float* Bm = &BC[lb * 32];
                const float* Cm = Bm + 16;
                const size_t srow = (size_t)b * (D_INNER * STATE_W) + (size_t)d * STATE_W + D_CONV;
                const float4* ss = reinterpret_cast<const float4*>(rnn + srow);
                float4* os = reinterpret_cast<float4*>(ost + srow);
                float y = 0.f;
#pragma unroll
                for (int q = 0; q < 4; q++) {
                    float4 s = ss[q];
                    float sn[4] = {s.x, s.y, s.z, s.w};
                    float on[4];
#pragma unroll
                    for (int i = 0; i < 4; i++) {
                        const int n = q * 4 + i;
                        const float sv = sn[i] * __expf(-dt * eA[n]) + dtxc * Bm[n];
                        on[i] = sv;
                        y += sv * Cm[n];
                    }
                    os[q] = make_float4(on[0], on[1], on[2], on[3]);
                }
                y = (y + Dp[d] * xcv) * gz_[bd];
                yo[e] = y;
            }
            // write split y (pairs are adjacent d)
            bf16 h0, l0, h1, l1, h2, l2, h3, l3;
            bsplit(yo[0], h0, l0); bsplit(yo[1], h1, l1);
            bsplit(yo[2], h2, l2); bsplit(yo[3], h3, l3);
            __nv_bfloat162 ha = {h0, h1}, hb = {h2, h3};
            __nv_bfloat162 la = {l0, l1}, lb = {l2, l3};
            *reinterpret_cast<uint32_t*>(&yh[(size_t)mrb * D_INNER + nc])       = *(uint32_t*)&ha;
            *reinterpret_cast<uint32_t*>(&yh[(size_t)(mrb + 8) * D_INNER + nc]) = *(uint32_t*)&hb;
            *reinterpret_cast<uint32_t*>(&yl[(size_t)mrb * D_INNER + nc])       = *(uint32_t*)&la;
            *reinterpret_cast<uint32_t*>(&yl[(size_t)(mrb + 8) * D_INNER + nc]) = *(uint32_t*)&lb;
        }
    }
}

// ---------------- mega prep: all plain splits + xdb zero ----------------
__device__ __forceinline__ void split4(const float* in, bf16* hi, bf16* lo, int i) {
    float4 v = reinterpret_cast<const float4*>(in)[i];
    bf16 h0, l0, h1, l1, h2, l2, h3, l3;
    bsplit(v.x, h0, l0); bsplit(v.y, h1, l1);
    bsplit(v.z, h2, l2); bsplit(v.w, h3, l3);
    __nv_bfloat162 hA = {h0, h1}, hB = {h2, h3};
    __nv_bfloat162 lA = {l0, l1}, lB = {l2, l3};
    uint2 hu = {*(uint32_t*)&hA, *(uint32_t*)&hB};
    uint2 lu = {*(uint32_t*)&lA, *(uint32_t*)&lB};
    reinterpret_cast<uint2*>(hi)[i] = hu;
    reinterpret_cast<uint2*>(lo)[i] = lu;
}

__global__ void __launch_bounds__(256)
prep_kernel(const float* __restrict__ x, const float* __restrict__ w_inp,
            const float* __restrict__ in_proj, const float* __restrict__ x_proj,
            const float* __restrict__ dt_proj,
            bf16* xH, bf16* xL, bf16* wiH, bf16* wiL, bf16* ipH, bf16* ipL,
            bf16* w4H, bf16* w4L, bf16* w5H, bf16* w5L, float* __restrict__ xdb)
{
    const int blk = blockIdx.x;
    const int tid = threadIdx.x;
    if (blk < 1024) {                       // x: 262144 f4
        split4(x, xH, xL, blk * 256 + tid);
    } else if (blk < 1536) {                // w_inp: 131072 f4
        split4(w_inp, wiH, wiL, (blk - 1024) * 256 + tid);
    } else if (blk < 5632) {                // in_proj: 1048576 f4
        split4(in_proj, ipH, ipL, (blk - 1536) * 256 + tid);
    } else if (blk < 5824) {                // x_proj: 49152 f4
        split4(x_proj, w4H, w4L, (blk - 5632) * 256 + tid);
    } else if (blk < 5952) {                // dt_proj: 32768 f4
        split4(dt_proj, w5H, w5L, (blk - 5824) * 256 + tid);
    } else {                                // zero xdb: 49152 f4
        reinterpret_cast<float4*>(xdb)[(blk - 5952) * 256 + tid] =
            make_float4(0.f, 0.f, 0.f, 0.f);
    }
}

// ---------------- transpose + split: KxN fp32 -> NxK bf16 hi/lo ----------------
__global__ void __launch_bounds__(256)
tsplit_kernel(const float* __restrict__ in, bf16* __restrict__ hi,
              bf16* __restrict__ lo, int K, int N)
{
    __shared__ float t[32][33];
    const int k0 = blockIdx.y * 32, n0 = blockIdx.x * 32;
    const int tx = threadIdx.x & 31, ty = threadIdx.x >> 5;
#pragma unroll
    for (int j = ty; j < 32; j += 8)
        t[j][tx] = in[(size_t)(k0 + j) * N + n0 + tx];
    __syncthreads();
#pragma unroll
    for (int j = ty; j < 32; j += 8) {
        float v = t[tx][j];
        bf16 h, l; bsplit(v, h, l);
        hi[(size_t)(n0 + j) * K + k0 + tx] = h;
        lo[(size_t)(n0 + j) * K + k0 + tx] = l;
    }
}

// ---------------- bz[n] = sum_j b_inp[j] * in_proj_w[n, j] ----------------
__global__ void __launch_bounds__(256)
bz_kernel(const float* __restrict__ b, const float* __restrict__ W,
          float* __restrict__ bz)
{
    const int w = (blockIdx.x * 256 + threadIdx.x) >> 5;
    const int lane = threadIdx.x & 31;
    if (w >= 2 * D_INNER) return;
    float s = 0.f;
    for (int j = lane; j < D_MODEL; j += 32)
        s += b[j] * W[(size_t)w * D_MODEL + j];
#pragma unroll
    for (int o = 16; o; o >>= 1) s += __shfl_xor_sync(0xFFFFFFFFu, s, o);
    if (lane == 0) bz[w] = s;
}

// ---------------- launch ----------------
#define GETP(sym, var) float* var; cudaGetSymbolAddress((void**)&var, sym)
#define GETB(sym, var) bf16* var; cudaGetSymbolAddress((void**)&var, sym)

extern "C" void kernel_launch(void* const* d_in, const int* in_sizes, int n_in,
                              void* d_out, int out_size)
{
    const float* x          = (const float*)d_in[0];
    const float* rnn        = (const float*)d_in[1];
    const float* w_inp      = (const float*)d_in[2];
    const float* b_inp      = (const float*)d_in[3];
    const float* w_outp     = (const float*)d_in[4];
    const float* b_outp     = (const float*)d_in[5];
    const float* in_proj_w  = (const float*)d_in[6];
    const float* conv_w     = (const float*)d_in[7];
    const float* conv_b     = (const float*)d_in[8];
    const float* x_proj_w   = (const float*)d_in[9];
    const float* dt_proj_w  = (const float*)d_in[10];
    const float* dt_proj_b  = (const float*)d_in[11];
    const float* A_log      = (const float*)d_in[12];
    const float* Dp         = (const float*)d_in[13];
    const float* out_proj_w = (const float*)d_in[14];

    float* out = (float*)d_out;
    float* out_states = out + (size_t)BATCH * OUT_SIZE;

    GETP(g_xc, p_xc);   GETP(g_gz, p_gz);   GETP(g_xdb, p_xdb);  GETP(g_bz, p_bz);
    GETB(g_x_hi, xH);   GETB(g_x_lo, xL);
    GETB(g_xc_hi, xcH); GETB(g_xc_lo, xcL);
    GETB(g_y_hi, yH);   GETB(g_y_lo, yL);
    GETB(g_wi_hi, wiH); GETB(g_wi_lo, wiL);
    GETB(g_ip_hi, ipH); GETB(g_ip_lo, ipL);
    GETB(g_wxz_hi, wxH); GETB(g_wxz_lo, wxL);
    GETB(g_w4_hi, w4H); GETB(g_w4_lo, w4L);
    GETB(g_w5_hi, w5H); GETB(g_w5_lo, w5L);
    GETB(g_opT_hi, opH); GETB(g_opT_lo, opL);
    GETB(g_woT_hi, woH); GETB(g_woT_lo, woL);
    GETB(g_wf_hi, wfH); GETB(g_wf_lo, wfL);

    cudaFuncSetAttribute(bgemm<0, false, true >, cudaFuncAttributeMaxDynamicSharedMemorySize, TG_SMEM);
    cudaFuncSetAttribute(bgemm<1, false, false>, cudaFuncAttributeMaxDynamicSharedMemorySize, TG_SMEM);
    cudaFuncSetAttribute(bgemm<3, false, false>, cudaFuncAttributeMaxDynamicSharedMemorySize, TG_SMEM);
    cudaFuncSetAttribute(bgemm<0, true,  false>, cudaFuncAttributeMaxDynamicSharedMemorySize, TG_SMEM);
    cudaFuncSetAttribute(dtssm_kernel, cudaFuncAttributeMaxDynamicSharedMemorySize, DS_SMEM);

    dim3 blk(256);
#define NOFUSE nullptr, nullptr, nullptr, nullptr, nullptr, nullptr, nullptr, nullptr

    // 1) mega prep (all plain splits + xdb zero)
    prep_kernel<<<6144, blk>>>(x, w_inp, in_proj_w, x_proj_w, dt_proj_w,
                               xH, xL, wiH, wiL, ipH, ipL, w4H, w4L, w5H, w5L, p_xdb);
    // 2,3) transpose splits
    tsplit_kernel<<<dim3(D_INNER / 32, D_MODEL / 32), blk>>>(out_proj_w, opH, opL, D_MODEL, D_INNER);
    tsplit_kernel<<<dim3(OUT_SIZE / 32, D_MODEL / 32), blk>>>(w_outp, woH, woL, D_MODEL, OUT_SIZE);
    // 4) bz = b_inp @ in_proj_w^T
    bz_kernel<<<(2 * D_INNER * 32 + 255) / 256, blk>>>(b_inp, in_proj_w, p_bz);
    // 5) W12 = in_proj @ w_inp^T(NxK both)  -> [4096 x 512] split
    bgemm<0, false, true><<<dim3(IN_SIZE / 128, 2 * D_INNER / 128), blk, TG_SMEM>>>(
        ipH, ipL, wiH, wiL, nullptr, wxH, wxL, nullptr,
        2 * D_INNER, IN_SIZE, D_MODEL, D_MODEL, D_MODEL, IN_SIZE, NOFUSE);
    // 6) Wf = w_outp^T @ out_proj  -> [512 x 2048] split
    bgemm<0, false, true><<<dim3(D_INNER / 128, OUT_SIZE / 128), blk, TG_SMEM>>>(
        woH, woL, opH, opL, nullptr, wfH, wfL, nullptr,
        OUT_SIZE, D_INNER, D_MODEL, D_MODEL, D_MODEL, D_INNER, NOFUSE);
    // 7) xz GEMM + fused conv / silu(z) epilogue
    bgemm<3, false, false><<<dim3(2 * D_INNER / 128, BATCH / 128), blk, TG_SMEM>>>(
        xH, xL, wxH, wxL, nullptr, nullptr, nullptr, p_bz,
        BATCH, 2 * D_INNER, IN_SIZE, IN_SIZE, IN_SIZE, 2 * D_INNER,
        rnn, conv_w, conv_b, out_states, p_xc, xcH, xcL, p_gz);
    // 8) xdb = xc @ x_proj^T (split-K=8, atomics)
    bgemm<0, true, false><<<dim3(1, BATCH / 128, 8), blk, TG_SMEM>>>(
        xcH, xcL, w4H, w4L, p_xdb, nullptr, nullptr, nullptr,
        BATCH, XDB_COLS, D_INNER, D_INNER, D_INNER, XDB_COLS, NOFUSE);
    // 9) fused dt GEMM + SSM update -> out_states + split y
    dtssm_kernel<<<dim3(D_INNER / 128, BATCH / 128), blk, DS_SMEM>>>(
        p_xdb, w5H, w5L, dt_proj_b, A_log, Dp, p_xc, p_gz, rnn,
        out_states, yH, yL);
    // 10) out = y @ Wf^T + b_outp
    bgemm<1, false, false><<<dim3(OUT_SIZE / 128, BATCH / 128), blk, TG_SMEM>>>(
        yH, yL, wfH, wfL, out, nullptr, nullptr, b_outp,
        BATCH, OUT_SIZE, D_INNER, D_INNER, D_INNER, OUT_SIZE, NOFUSE);
}

// round 9
// speedup vs baseline: 1.5233x; 1.5233x over previous
#include <cuda_runtime.h>
#include <cuda_bf16.h>
#include <math.h>
#include <stdint.h>

#define D_MODEL   1024
#define D_STATE   16
#define D_CONV    4
#define D_INNER   2048
#define DT_RANK   64
#define IN_SIZE   512
#define OUT_SIZE  512
#define BATCH     2048
#define XDB_COLS  96
#define STATE_W   20

typedef __nv_bfloat16 bf16;

// ---------------- fp32 scratch ----------------
__device__ float g_xz[BATCH * 2 * D_INNER];
__device__ float g_xc[BATCH * D_INNER];
__device__ float g_xdb[BATCH * XDB_COLS];
__device__ float g_dt[BATCH * D_INNER];
__device__ float g_bz[2 * D_INNER];
// ---------------- bf16 split scratch ----------------
__device__ bf16 g_x_hi[BATCH * IN_SIZE],   g_x_lo[BATCH * IN_SIZE];
__device__ bf16 g_xc_hi[BATCH * D_INNER],  g_xc_lo[BATCH * D_INNER];
__device__ bf16 g_y_hi[BATCH * D_INNER],   g_y_lo[BATCH * D_INNER];
__device__ bf16 g_xdb_hi[BATCH * XDB_COLS], g_xdb_lo[BATCH * XDB_COLS];
__device__ bf16 g_wi_hi[IN_SIZE * D_MODEL],     g_wi_lo[IN_SIZE * D_MODEL];
__device__ bf16 g_ip_hi[2 * D_INNER * D_MODEL], g_ip_lo[2 * D_INNER * D_MODEL];
__device__ bf16 g_wxz_hi[2 * D_INNER * IN_SIZE], g_wxz_lo[2 * D_INNER * IN_SIZE];
__device__ bf16 g_w4_hi[XDB_COLS * D_INNER],    g_w4_lo[XDB_COLS * D_INNER];
__device__ bf16 g_w5_hi[D_INNER * DT_RANK],     g_w5_lo[D_INNER * DT_RANK];
__device__ bf16 g_opT_hi[D_INNER * D_MODEL],    g_opT_lo[D_INNER * D_MODEL];
__device__ bf16 g_woT_hi[OUT_SIZE * D_MODEL],   g_woT_lo[OUT_SIZE * D_MODEL];
__device__ bf16 g_wf_hi[OUT_SIZE * D_INNER],    g_wf_lo[OUT_SIZE * D_INNER];

// ---------------- helpers ----------------
__device__ __forceinline__ float softplusf(float x) {
    return (x > 0.f) ? (x + log1pf(__expf(-x))) : log1pf(__expf(x));
}
__device__ __forceinline__ float siluf(float x) {
    return x / (1.f + __expf(-x));
}
__device__ __forceinline__ void bsplit(float v, bf16& h, bf16& l) {
    h = __float2bfloat16_rn(v);
    l = __float2bfloat16_rn(v - __bfloat162float(h));
}
__device__ __forceinline__ void mmabf(float* c, const uint32_t* a, const uint32_t* b) {
    asm volatile(
        "mma.sync.aligned.m16n8k16.row.col.f32.bf16.bf16.f32 "
        "{%0,%1,%2,%3}, {%4,%5,%6,%7}, {%8,%9}, {%0,%1,%2,%3};"
        : "+f"(c[0]), "+f"(c[1]), "+f"(c[2]), "+f"(c[3])
        : "r"(a[0]), "r"(a[1]), "r"(a[2]), "r"(a[3]), "r"(b[0]), "r"(b[1]));
}
__device__ __forceinline__ void cpa16(uint32_t dst, const void* src, bool p) {
    int sz = p ? 16 : 0;
    asm volatile("cp.async.cg.shared.global [%0], [%1], 16, %2;\n"
                 :: "r"(dst), "l"(src), "r"(sz));
}

// ======================================================================
// 2xBF16-split tensor GEMM (R4/R7-proven). C[M,N] = A[M,K] @ B[N,K]^T.
// BM=BN=128, BK=64 elem, 256 thr, warps 4(m)x2(n), warp tile 32x64.
// cp.async 2-stage. EPI: 0 none, 1 +bias, 2 +bias+softplus.
// ======================================================================
#define TG_SMEM (2 * 4 * 128 * 36 * 4)   // 147456 B

template<int EPI, bool SPLITK, bool WSPLIT>
__global__ void __launch_bounds__(256, 1)
bgemm(const bf16* __restrict__ Ahi, const bf16* __restrict__ Alo,
      const bf16* __restrict__ Bhi, const bf16* __restrict__ Blo,
      float* __restrict__ C, bf16* __restrict__ Chi, bf16* __restrict__ Clo,
      const float* __restrict__ bias,
      int M, int N, int K, int lda, int ldb, int ldc)
{
    extern __shared__ uint32_t smbuf[];
    constexpr int TSZ = 128 * 36;
    constexpr int STAGE = 4 * TSZ;

    const uint32_t* A32h = reinterpret_cast<const uint32_t*>(Ahi);
    const uint32_t* A32l = reinterpret_cast<const uint32_t*>(Alo);
    const uint32_t* B32h = reinterpret_cast<const uint32_t*>(Bhi);
    const uint32_t* B32l = reinterpret_cast<const uint32_t*>(Blo);
    const int ldap = lda >> 1, ldbp = ldb >> 1;

    const int tid  = threadIdx.x;
    const int lane = tid & 31;
    const int warp = tid >> 5;
    const int wm   = warp & 3;
    const int wn   = warp >> 2;
    const int m0   = blockIdx.y * 128;
    const int n0   = blockIdx.x * 128;
    const int Kc   = SPLITK ? (K / gridDim.z) : K;
    const int k0b  = SPLITK ? (blockIdx.z * Kc) : 0;
    const int T    = Kc / 64;

    const int lr = tid >> 3;
    const int lc = (tid & 7) * 4;

    float acc[2][8][4];
#pragma unroll
    for (int i = 0; i < 2; i++)
#pragma unroll
        for (int j = 0; j < 8; j++)
#pragma unroll
            for (int q = 0; q < 4; q++) acc[i][j][q] = 0.f;

    auto fill = [&](int t, int st) {
        uint32_t* Ah = smbuf + st * STAGE;
        uint32_t* Al = Ah + TSZ;
        uint32_t* Bh = Al + TSZ;
        uint32_t* Bl = Bh + TSZ;
        const int kp0 = (k0b + t * 64) >> 1;
#pragma unroll
        for (int it = 0; it < 4; it++) {
            const int row = lr + it * 32;
            const size_t g = (size_t)(m0 + row) * ldap + kp0 + lc;
            cpa16((uint32_t)__cvta_generic_to_shared(&Ah[row * 36 + lc]), A32h + g, true);
            cpa16((uint32_t)__cvta_generic_to_shared(&Al[row * 36 + lc]), A32l + g, true);
        }
#pragma unroll
        for (int it = 0; it < 4; it++) {
            const int row = lr + it * 32;
            const bool p = SPLITK ? ((n0 + row) < N) : true;
            const size_t g = (size_t)(n0 + row) * ldbp + kp0 + lc;
            cpa16((uint32_t)__cvta_generic_to_shared(&Bh[row * 36 + lc]), B32h + g, p);
            cpa16((uint32_t)__cvta_generic_to_shared(&Bl[row * 36 + lc]), B32l + g, p);
        }
    };

    auto compute = [&](int st) {
        uint32_t* Ah = smbuf + st * STAGE;
        uint32_t* Al = Ah + TSZ;
        uint32_t* Bh = Al + TSZ;
        uint32_t* Bl = Bh + TSZ;
#pragma unroll
        for (int ks = 0; ks < 32; ks += 8) {
            uint32_t ah[2][4], al[2][4];
#pragma unroll
            for (int mt = 0; mt < 2; mt++) {
                const int mr = wm * 32 + mt * 16 + (lane >> 2);
                const int kc = ks + (lane & 3);
                ah[mt][0] = Ah[mr * 36 + kc];
                ah[mt][1] = Ah[(mr + 8) * 36 + kc];
                ah[mt][2] = Ah[mr * 36 + kc + 4];
                ah[mt][3] = Ah[(mr + 8) * 36 + kc + 4];
                al[mt][0] = Al[mr * 36 + kc];
                al[mt][1] = Al[(mr + 8) * 36 + kc];
                al[mt][2] = Al[mr * 36 + kc + 4];
                al[mt][3] = Al[(mr + 8) * 36 + kc + 4];
            }
            uint32_t bh[8][2], bl[8][2];
#pragma unroll
            for (int nt = 0; nt < 8; nt++) {
                const int nc = wn * 64 + nt * 8 + (lane >> 2);
                const int kc = ks + (lane & 3);
                bh[nt][0] = Bh[nc * 36 + kc];
                bh[nt][1] = Bh[nc * 36 + kc + 4];
                bl[nt][0] = Bl[nc * 36 + kc];
                bl[nt][1] = Bl[nc * 36 + kc + 4];
            }
#pragma unroll
            for (int mt = 0; mt < 2; mt++)
#pragma unroll
                for (int nt = 0; nt < 8; nt++) {
                    mmabf(acc[mt][nt], ah[mt], bl[nt]);
                    mmabf(acc[mt][nt], al[mt], bh[nt]);
                    mmabf(acc[mt][nt], ah[mt], bh[nt]);
                }
        }
    };

    fill(0, 0);
    asm volatile("cp.async.commit_group;" ::: "memory");
    for (int t = 0; t < T; t++) {
        if (t + 1 < T) {
            fill(t + 1, (t + 1) & 1);
            asm volatile("cp.async.commit_group;" ::: "memory");
            asm volatile("cp.async.wait_group 1;" ::: "memory");
        } else {
            asm volatile("cp.async.wait_group 0;" ::: "memory");
        }
        __syncthreads();
        compute(t & 1);
        __syncthreads();
    }

    // ---- epilogue
#pragma unroll
    for (int mt = 0; mt < 2; mt++) {
        const int mr = m0 + wm * 32 + mt * 16 + (lane >> 2);
#pragma unroll
        for (int nt = 0; nt < 8; nt++) {
            const int nc = n0 + wn * 64 + nt * 8 + (lane & 3) * 2;
            float v0 = acc[mt][nt][0], v1 = acc[mt][nt][1];
            float v2 = acc[mt][nt][2], v3 = acc[mt][nt][3];
            if (SPLITK) {
                if (nc < N) {
                    atomicAdd(&C[(size_t)mr * ldc + nc], v0);
                    atomicAdd(&C[(size_t)mr * ldc + nc + 1], v1);
                    atomicAdd(&C[(size_t)(mr + 8) * ldc + nc], v2);
                    atomicAdd(&C[(size_t)(mr + 8) * ldc + nc + 1], v3);
                }
                continue;
            }
            if (EPI >= 1) {
                const float b0 = bias[nc], b1 = bias[nc + 1];
                v0 += b0; v1 += b1; v2 += b0; v3 += b1;
            }
            if (EPI == 2) {
                v0 = softplusf(v0); v1 = softplusf(v1);
                v2 = softplusf(v2); v3 = softplusf(v3);
            }
            if (WSPLIT) {
                bf16 h0, l0, h1, l1, h2, l2, h3, l3;
                bsplit(v0, h0, l0); bsplit(v1, h1, l1);
                bsplit(v2, h2, l2); bsplit(v3, h3, l3);
                __nv_bfloat162 ha = {h0, h1}, hb = {h2, h3};
                __nv_bfloat162 la = {l0, l1}, lb = {l2, l3};
                *reinterpret_cast<uint32_t*>(&Chi[(size_t)mr * ldc + nc])       = *(uint32_t*)&ha;
                *reinterpret_cast<uint32_t*>(&Chi[(size_t)(mr + 8) * ldc + nc]) = *(uint32_t*)&hb;
                *reinterpret_cast<uint32_t*>(&Clo[(size_t)mr * ldc + nc])       = *(uint32_t*)&la;
                *reinterpret_cast<uint32_t*>(&Clo[(size_t)(mr + 8) * ldc + nc]) = *(uint32_t*)&lb;
            } else {
                *reinterpret_cast<float2*>(&C[(size_t)mr * ldc + nc])       = make_float2(v0, v1);
                *reinterpret_cast<float2*>(&C[(size_t)(mr + 8) * ldc + nc]) = make_float2(v2, v3);
            }
        }
    }
}

// ---------------- split helper + mega prep ----------------
__device__ __forceinline__ void split4(const float* in, bf16* hi, bf16* lo, int i) {
    float4 v = reinterpret_cast<const float4*>(in)[i];
    bf16 h0, l0, h1, l1, h2, l2, h3, l3;
    bsplit(v.x, h0, l0); bsplit(v.y, h1, l1);
    bsplit(v.z, h2, l2); bsplit(v.w, h3, l3);
    __nv_bfloat162 hA = {h0, h1}, hB = {h2, h3};
    __nv_bfloat162 lA = {l0, l1}, lB = {l2, l3};
    uint2 hu = {*(uint32_t*)&hA, *(uint32_t*)&hB};
    uint2 lu = {*(uint32_t*)&lA, *(uint32_t*)&lB};
    reinterpret_cast<uint2*>(hi)[i] = hu;
    reinterpret_cast<uint2*>(lo)[i] = lu;
}

__global__ void __launch_bounds__(256)
prep_kernel(const float* __restrict__ x, const float* __restrict__ w_inp,
            const float* __restrict__ in_proj, const float* __restrict__ x_proj,
            const float* __restrict__ dt_proj,
            bf16* xH, bf16* xL, bf16* wiH, bf16* wiL, bf16* ipH, bf16* ipL,
            bf16* w4H, bf16* w4L, bf16* w5H, bf16* w5L, float* __restrict__ xdb)
{
    const int blk = blockIdx.x;
    const int tid = threadIdx.x;
    if (blk < 1024) {                       // x: 262144 f4
        split4(x, xH, xL, blk * 256 + tid);
    } else if (blk < 1536) {                // w_inp: 131072 f4
        split4(w_inp, wiH, wiL, (blk - 1024) * 256 + tid);
    } else if (blk < 5632) {                // in_proj: 1048576 f4
        split4(in_proj, ipH, ipL, (blk - 1536) * 256 + tid);
    } else if (blk < 5824) {                // x_proj: 49152 f4
        split4(x_proj, w4H, w4L, (blk - 5632) * 256 + tid);
    } else if (blk < 5952) {                // dt_proj: 32768 f4
        split4(dt_proj, w5H, w5L, (blk - 5824) * 256 + tid);
    } else {                                // zero xdb: 49152 f4
        reinterpret_cast<float4*>(xdb)[(blk - 5952) * 256 + tid] =
            make_float4(0.f, 0.f, 0.f, 0.f);
    }
}

// ---------------- plain split (for xdb after GEMM4) ----------------
__global__ void __launch_bounds__(256)
split_kernel(const float* __restrict__ in, bf16* __restrict__ hi,
             bf16* __restrict__ lo, int n4)
{
    int i = blockIdx.x * 256 + threadIdx.x;
    if (i < n4) split4(in, hi, lo, i);
}

// ---------------- transpose + split: KxN fp32 -> NxK bf16 hi/lo ----------------
__global__ void __launch_bounds__(256)
tsplit_kernel(const float* __restrict__ in, bf16* __restrict__ hi,
              bf16* __restrict__ lo, int K, int N)
{
    __shared__ float t[32][33];
    const int k0 = blockIdx.y * 32, n0 = blockIdx.x * 32;
    const int tx = threadIdx.x & 31, ty = threadIdx.x >> 5;
#pragma unroll
    for (int j = ty; j < 32; j += 8)
        t[j][tx] = in[(size_t)(k0 + j) * N + n0 + tx];
    __syncthreads();
#pragma unroll
    for (int j = ty; j < 32; j += 8) {
        float v = t[tx][j];
        bf16 h, l; bsplit(v, h, l);
        hi[(size_t)(n0 + j) * K + k0 + tx] = h;
        lo[(size_t)(n0 + j) * K + k0 + tx] = l;
    }
}

// ---------------- bz[n] = sum_j b_inp[j] * in_proj_w[n, j] ----------------
__global__ void __launch_bounds__(256)
bz_kernel(const float* __restrict__ b, const float* __restrict__ W,
          float* __restrict__ bz)
{
    const int w = (blockIdx.x * 256 + threadIdx.x) >> 5;
    const int lane = threadIdx.x & 31;
    if (w >= 2 * D_INNER) return;
    float s = 0.f;
    for (int j = lane; j < D_MODEL; j += 32)
        s += b[j] * W[(size_t)w * D_MODEL + j];
#pragma unroll
    for (int o = 16; o; o >>= 1) s += __shfl_xor_sync(0xFFFFFFFFu, s, o);
    if (lane == 0) bz[w] = s;
}

// ---------------- conv-shift + silu: xc ONLY (no state write) ----------------
__global__ void __launch_bounds__(256)
conv_kernel(const float* __restrict__ rnn, const float* __restrict__ xz,
            const float* __restrict__ conv_w, const float* __restrict__ conv_b,
            float* __restrict__ xc, bf16* __restrict__ xch, bf16* __restrict__ xcl)
{
    const size_t idx = (size_t)blockIdx.x * 256 + threadIdx.x;
    const int b = (int)(idx / D_INNER);
    const int d = (int)(idx % D_INNER);
    const size_t srow = (size_t)b * (D_INNER * STATE_W) + (size_t)d * STATE_W;

    float4 cs = *reinterpret_cast<const float4*>(rnn + srow);
    float xi = xz[(size_t)b * (2 * D_INNER) + d];
    float4 w = *reinterpret_cast<const float4*>(conv_w + d * 4);

    float v = cs.y * w.x + cs.z * w.y + cs.w * w.z + xi * w.w + conv_b[d];
    float s = siluf(v);
    xc[idx] = s;
    bf16 h, l; bsplit(s, h, l);
    xch[idx] = h; xcl[idx] = l;
}

// ---------------- full-row state kernel: conv-state + SSM + y ----------------
// Reads the full 80B rnn row coalesced, writes the full 80B new row + split y.
__global__ void __launch_bounds__(256)
state_kernel(const float* __restrict__ rnn, const float* __restrict__ xz,
             const float* __restrict__ xdb, const float* __restrict__ dt_,
             const float* __restrict__ xc_, const float* __restrict__ A_log,
             const float* __restrict__ Dp,
             float* __restrict__ ost, bf16* __restrict__ yh, bf16* __restrict__ yl)
{
    const int b = blockIdx.y;
    const int d = blockIdx.x * 256 + threadIdx.x;

    __shared__ float sBC[32];
    if (threadIdx.x < 32) sBC[threadIdx.x] = xdb[(size_t)b * XDB_COLS + DT_RANK + threadIdx.x];
    __syncthreads();

    const size_t bd = (size_t)b * D_INNER + d;
    const float dt = dt_[bd];
    const float xc = xc_[bd];
    const float xi = xz[(size_t)b * (2 * D_INNER) + d];
    const float z  = xz[(size_t)b * (2 * D_INNER) + D_INNER + d];
    const float dtxc = dt * xc;

    const size_t srow = (size_t)b * (D_INNER * STATE_W) + (size_t)d * STATE_W;
    const float4* rr = reinterpret_cast<const float4*>(rnn + srow);   // 5 x float4
    float4* wr = reinterpret_cast<float4*>(ost + srow);
    const float4* Al = reinterpret_cast<const float4*>(A_log + d * D_STATE);

    // row[0]: conv state
    float4 cs = rr[0];
    wr[0] = make_float4(cs.y, cs.z, cs.w, xi);

    // rows[1..4]: ssm states
    float y = 0.f;
#pragma unroll
    for (int q = 0; q < 4; q++) {
        float4 s = rr[q + 1];
        float4 a = Al[q];
        float sn[4] = {s.x, s.y, s.z, s.w};
        float an[4] = {a.x, a.y, a.z, a.w};
        float on[4];
#pragma unroll
        for (int i = 0; i < 4; i++) {
            const int n = q * 4 + i;
            const float dA = __expf(-dt * __expf(an[i]));
            const float sv = sn[i] * dA + dtxc * sBC[n];
            on[i] = sv;
            y += sv * sBC[16 + n];
        }
        wr[q + 1] = make_float4(on[0], on[1], on[2], on[3]);
    }
    y += Dp[d] * xc;
    y *= siluf(z);
    bf16 h, l; bsplit(y, h, l);
    yh[bd] = h; yl[bd] = l;
}

// ---------------- launch ----------------
#define GETP(sym, var) float* var; cudaGetSymbolAddress((void**)&var, sym)
#define GETB(sym, var) bf16* var; cudaGetSymbolAddress((void**)&var, sym)

extern "C" void kernel_launch(void* const* d_in, const int* in_sizes, int n_in,
                              void* d_out, int out_size)
{
    const float* x          = (const float*)d_in[0];
    const float* rnn        = (const float*)d_in[1];
    const float* w_inp      = (const float*)d_in[2];
    const float* b_inp      = (const float*)d_in[3];
    const float* w_outp     = (const float*)d_in[4];
    const float* b_outp     = (const float*)d_in[5];
    const float* in_proj_w  = (const float*)d_in[6];
    const float* conv_w     = (const float*)d_in[7];
    const float* conv_b     = (const float*)d_in[8];
    const float* x_proj_w   = (const float*)d_in[9];
    const float* dt_proj_w  = (const float*)d_in[10];
    const float* dt_proj_b  = (const float*)d_in[11];
    const float* A_log      = (const float*)d_in[12];
    const float* Dp         = (const float*)d_in[13];
    const float* out_proj_w = (const float*)d_in[14];

    float* out = (float*)d_out;
    float* out_states = out + (size_t)BATCH * OUT_SIZE;

    GETP(g_xz, p_xz);   GETP(g_xc, p_xc);   GETP(g_xdb, p_xdb);  GETP(g_dt, p_dt);
    GETP(g_bz, p_bz);
    GETB(g_x_hi, xH);   GETB(g_x_lo, xL);
    GETB(g_xc_hi, xcH); GETB(g_xc_lo, xcL);
    GETB(g_y_hi, yH);   GETB(g_y_lo, yL);
    GETB(g_xdb_hi, xdH); GETB(g_xdb_lo, xdL);
    GETB(g_wi_hi, wiH); GETB(g_wi_lo, wiL);
    GETB(g_ip_hi, ipH); GETB(g_ip_lo, ipL);
    GETB(g_wxz_hi, wxH); GETB(g_wxz_lo, wxL);
    GETB(g_w4_hi, w4H); GETB(g_w4_lo, w4L);
    GETB(g_w5_hi, w5H); GETB(g_w5_lo, w5L);
    GETB(g_opT_hi, opH); GETB(g_opT_lo, opL);
    GETB(g_woT_hi, woH); GETB(g_woT_lo, woL);
    GETB(g_wf_hi, wfH); GETB(g_wf_lo, wfL);

    cudaFuncSetAttribute(bgemm<0, false, true >, cudaFuncAttributeMaxDynamicSharedMemorySize, TG_SMEM);
    cudaFuncSetAttribute(bgemm<1, false, false>, cudaFuncAttributeMaxDynamicSharedMemorySize, TG_SMEM);
    cudaFuncSetAttribute(bgemm<2, false, false>, cudaFuncAttributeMaxDynamicSharedMemorySize, TG_SMEM);
    cudaFuncSetAttribute(bgemm<0, true,  false>, cudaFuncAttributeMaxDynamicSharedMemorySize, TG_SMEM);

    dim3 blk(256);

    // 1) mega prep (plain splits + xdb zero)
    prep_kernel<<<6144, blk>>>(x, w_inp, in_proj_w, x_proj_w, dt_proj_w,
                               xH, xL, wiH, wiL, ipH, ipL, w4H, w4L, w5H, w5L, p_xdb);
    // 2,3) transpose splits
    tsplit_kernel<<<dim3(D_INNER / 32, D_MODEL / 32), blk>>>(out_proj_w, opH, opL, D_MODEL, D_INNER);
    tsplit_kernel<<<dim3(OUT_SIZE / 32, D_MODEL / 32), blk>>>(w_outp, woH, woL, D_MODEL, OUT_SIZE);
    // 4) bz = b_inp @ in_proj_w^T
    bz_kernel<<<(2 * D_INNER * 32 + 255) / 256, blk>>>(b_inp, in_proj_w, p_bz);
    // 5) W12 = in_proj @ w_inp^T -> [4096 x 512] split
    bgemm<0, false, true><<<dim3(IN_SIZE / 128, 2 * D_INNER / 128), blk, TG_SMEM>>>(
        ipH, ipL, wiH, wiL, nullptr, wxH, wxL, nullptr,
        2 * D_INNER, IN_SIZE, D_MODEL, D_MODEL, D_MODEL, IN_SIZE);
    // 6) Wf = w_outp^T @ out_proj -> [512 x 2048] split
    bgemm<0, false, true><<<dim3(D_INNER / 128, OUT_SIZE / 128), blk, TG_SMEM>>>(
        woH, woL, opH, opL, nullptr, wfH, wfL, nullptr,
        OUT_SIZE, D_INNER, D_MODEL, D_MODEL, D_MODEL, D_INNER);
    // 7) xz = x @ W12^T + bz  (2048x4096, K=512)
    bgemm<1, false, false><<<dim3(2 * D_INNER / 128, BATCH / 128), blk, TG_SMEM>>>(
        xH, xL, wxH, wxL, p_xz, nullptr, nullptr, p_bz,
        BATCH, 2 * D_INNER, IN_SIZE, IN_SIZE, IN_SIZE, 2 * D_INNER);
    // 8) conv -> xc only
    conv_kernel<<<(BATCH * D_INNER) / 256, blk>>>(rnn, p_xz, conv_w, conv_b, p_xc, xcH, xcL);
    // 9) xdb = xc @ x_proj^T (split-K=8, atomics)
    bgemm<0, true, false><<<dim3(1, BATCH / 128, 8), blk, TG_SMEM>>>(
        xcH, xcL, w4H, w4L, p_xdb, nullptr, nullptr, nullptr,
        BATCH, XDB_COLS, D_INNER, D_INNER, D_INNER, XDB_COLS);
    // 10) split xdb
    split_kernel<<<(BATCH * XDB_COLS / 4 + 255) / 256, blk>>>(p_xdb, xdH, xdL, BATCH * XDB_COLS / 4);
    // 11) dt = softplus(xdb[:, :64] @ w5^T + dtb)
    bgemm<2, false, false><<<dim3(D_INNER / 128, BATCH / 128), blk, TG_SMEM>>>(
        xdH, xdL, w5H, w5L, p_dt, nullptr, nullptr, dt_proj_b,
        BATCH, D_INNER, DT_RANK, XDB_COLS, DT_RANK, D_INNER);
    // 12) full-row state update + y (coalesced 80B rows)
    state_kernel<<<dim3(D_INNER / 256, BATCH), blk>>>(
        rnn, p_xz, p_xdb, p_dt, p_xc, A_log, Dp, out_states, yH, yL);
    // 13) out = y @ Wf^T + b_outp
    bgemm<1, false, false><<<dim3(OUT_SIZE / 128, BATCH / 128), blk, TG_SMEM>>>(
        yH, yL, wfH, wfL, out, nullptr, nullptr, b_outp,
        BATCH, OUT_SIZE, D_INNER, D_INNER, D_INNER, OUT_SIZE);
}

// round 10
// speedup vs baseline: 1.7138x; 1.1250x over previous
#include <cuda_runtime.h>
#include <cuda_bf16.h>
#include <math.h>
#include <stdint.h>

#define D_MODEL   1024
#define D_STATE   16
#define D_CONV    4
#define D_INNER   2048
#define DT_RANK   64
#define IN_SIZE   512
#define OUT_SIZE  512
#define BATCH     2048
#define XDB_COLS  96
#define STATE_W   20

typedef __nv_bfloat16 bf16;

// ---------------- fp32 scratch ----------------
__device__ float g_xz[BATCH * 2 * D_INNER];
__device__ float g_xc[BATCH * D_INNER];
__device__ float g_xdb[BATCH * XDB_COLS];
__device__ float g_bz[2 * D_INNER];
// ---------------- bf16 split scratch ----------------
__device__ bf16 g_x_hi[BATCH * IN_SIZE],   g_x_lo[BATCH * IN_SIZE];
__device__ bf16 g_xc_hi[BATCH * D_INNER],  g_xc_lo[BATCH * D_INNER];
__device__ bf16 g_y_hi[BATCH * D_INNER],   g_y_lo[BATCH * D_INNER];
__device__ bf16 g_wi_hi[IN_SIZE * D_MODEL],     g_wi_lo[IN_SIZE * D_MODEL];
__device__ bf16 g_ip_hi[2 * D_INNER * D_MODEL], g_ip_lo[2 * D_INNER * D_MODEL];
__device__ bf16 g_wxz_hi[2 * D_INNER * IN_SIZE], g_wxz_lo[2 * D_INNER * IN_SIZE];
__device__ bf16 g_w4_hi[XDB_COLS * D_INNER],    g_w4_lo[XDB_COLS * D_INNER];
__device__ bf16 g_opT_hi[D_INNER * D_MODEL],    g_opT_lo[D_INNER * D_MODEL];
__device__ bf16 g_woT_hi[OUT_SIZE * D_MODEL],   g_woT_lo[OUT_SIZE * D_MODEL];
__device__ bf16 g_wf_hi[OUT_SIZE * D_INNER],    g_wf_lo[OUT_SIZE * D_INNER];

// ---------------- helpers ----------------
__device__ __forceinline__ float softplusf(float x) {
    return (x > 0.f) ? (x + log1pf(__expf(-x))) : log1pf(__expf(x));
}
__device__ __forceinline__ float siluf(float x) {
    return x / (1.f + __expf(-x));
}
__device__ __forceinline__ void bsplit(float v, bf16& h, bf16& l) {
    h = __float2bfloat16_rn(v);
    l = __float2bfloat16_rn(v - __bfloat162float(h));
}
__device__ __forceinline__ void mmabf(float* c, const uint32_t* a, const uint32_t* b) {
    asm volatile(
        "mma.sync.aligned.m16n8k16.row.col.f32.bf16.bf16.f32 "
        "{%0,%1,%2,%3}, {%4,%5,%6,%7}, {%8,%9}, {%0,%1,%2,%3};"
        : "+f"(c[0]), "+f"(c[1]), "+f"(c[2]), "+f"(c[3])
        : "r"(a[0]), "r"(a[1]), "r"(a[2]), "r"(a[3]), "r"(b[0]), "r"(b[1]));
}
__device__ __forceinline__ void cpa16(uint32_t dst, const void* src, bool p) {
    int sz = p ? 16 : 0;
    asm volatile("cp.async.cg.shared.global [%0], [%1], 16, %2;\n"
                 :: "r"(dst), "l"(src), "r"(sz));
}

// ======================================================================
// 2xBF16-split tensor GEMM. C[M,N] = A[M,K] @ B[N,K]^T.
// BM=BN=128, BK=64 elem, 256 thr, warps 4(m)x2(n), warp tile 32x64.
// cp.async 2-stage. EPI: 0 none, 1 +bias. SPLITK: atomicAdd (+N guard).
// ======================================================================
#define TG_SMEM (2 * 4 * 128 * 36 * 4)   // 147456 B

template<int EPI, bool SPLITK, bool WSPLIT>
__global__ void __launch_bounds__(256, 1)
bgemm(const bf16* __restrict__ Ahi, const bf16* __restrict__ Alo,
      const bf16* __restrict__ Bhi, const bf16* __restrict__ Blo,
      float* __restrict__ C, bf16* __restrict__ Chi, bf16* __restrict__ Clo,
      const float* __restrict__ bias,
      int M, int N, int K, int lda, int ldb, int ldc)
{
    extern __shared__ uint32_t smbuf[];
    constexpr int TSZ = 128 * 36;
    constexpr int STAGE = 4 * TSZ;

    const uint32_t* A32h = reinterpret_cast<const uint32_t*>(Ahi);
    const uint32_t* A32l = reinterpret_cast<const uint32_t*>(Alo);
    const uint32_t* B32h = reinterpret_cast<const uint32_t*>(Bhi);
    const uint32_t* B32l = reinterpret_cast<const uint32_t*>(Blo);
    const int ldap = lda >> 1, ldbp = ldb >> 1;

    const int tid  = threadIdx.x;
    const int lane = tid & 31;
    const int warp = tid >> 5;
    const int wm   = warp & 3;
    const int wn   = warp >> 2;
    const int m0   = blockIdx.y * 128;
    const int n0   = blockIdx.x * 128;
    const int Kc   = SPLITK ? (K / gridDim.z) : K;
    const int k0b  = SPLITK ? (blockIdx.z * Kc) : 0;
    const int T    = Kc / 64;

    const int lr = tid >> 3;
    const int lc = (tid & 7) * 4;

    float acc[2][8][4];
#pragma unroll
    for (int i = 0; i < 2; i++)
#pragma unroll
        for (int j = 0; j < 8; j++)
#pragma unroll
            for (int q = 0; q < 4; q++) acc[i][j][q] = 0.f;

    auto fill = [&](int t, int st) {
        uint32_t* Ah = smbuf + st * STAGE;
        uint32_t* Al = Ah + TSZ;
        uint32_t* Bh = Al + TSZ;
        uint32_t* Bl = Bh + TSZ;
        const int kp0 = (k0b + t * 64) >> 1;
#pragma unroll
        for (int it = 0; it < 4; it++) {
            const int row = lr + it * 32;
            const size_t g = (size_t)(m0 + row) * ldap + kp0 + lc;
            cpa16((uint32_t)__cvta_generic_to_shared(&Ah[row * 36 + lc]), A32h + g, true);
            cpa16((uint32_t)__cvta_generic_to_shared(&Al[row * 36 + lc]), A32l + g, true);
        }
#pragma unroll
        for (int it = 0; it < 4; it++) {
            const int row = lr + it * 32;
            const bool p = SPLITK ? ((n0 + row) < N) : true;
            const size_t g = (size_t)(n0 + row) * ldbp + kp0 + lc;
            cpa16((uint32_t)__cvta_generic_to_shared(&Bh[row * 36 + lc]), B32h + g, p);
            cpa16((uint32_t)__cvta_generic_to_shared(&Bl[row * 36 + lc]), B32l + g, p);
        }
    };

    auto compute = [&](int st) {
        uint32_t* Ah = smbuf + st * STAGE;
        uint32_t* Al = Ah + TSZ;
        uint32_t* Bh = Al + TSZ;
        uint32_t* Bl = Bh + TSZ;
#pragma unroll
        for (int ks = 0; ks < 32; ks += 8) {
            uint32_t ah[2][4], al[2][4];
#pragma unroll
            for (int mt = 0; mt < 2; mt++) {
                const int mr = wm * 32 + mt * 16 + (lane >> 2);
                const int kc = ks + (lane & 3);
                ah[mt][0] = Ah[mr * 36 + kc];
                ah[mt][1] = Ah[(mr + 8) * 36 + kc];
                ah[mt][2] = Ah[mr * 36 + kc + 4];
                ah[mt][3] = Ah[(mr + 8) * 36 + kc + 4];
                al[mt][0] = Al[mr * 36 + kc];
                al[mt][1] = Al[(mr + 8) * 36 + kc];
                al[mt][2] = Al[mr * 36 + kc + 4];
                al[mt][3] = Al[(mr + 8) * 36 + kc + 4];
            }
            uint32_t bh[8][2], bl[8][2];
#pragma unroll
            for (int nt = 0; nt < 8; nt++) {
                const int nc = wn * 64 + nt * 8 + (lane >> 2);
                const int kc = ks + (lane & 3);
                bh[nt][0] = Bh[nc * 36 + kc];
                bh[nt][1] = Bh[nc * 36 + kc + 4];
                bl[nt][0] = Bl[nc * 36 + kc];
                bl[nt][1] = Bl[nc * 36 + kc + 4];
            }
#pragma unroll
            for (int mt = 0; mt < 2; mt++)
#pragma unroll
                for (int nt = 0; nt < 8; nt++) {
                    mmabf(acc[mt][nt], ah[mt], bl[nt]);
                    mmabf(acc[mt][nt], al[mt], bh[nt]);
                    mmabf(acc[mt][nt], ah[mt], bh[nt]);
                }
        }
    };

    fill(0, 0);
    asm volatile("cp.async.commit_group;" ::: "memory");
    for (int t = 0; t < T; t++) {
        if (t + 1 < T) {
            fill(t + 1, (t + 1) & 1);
            asm volatile("cp.async.commit_group;" ::: "memory");
            asm volatile("cp.async.wait_group 1;" ::: "memory");
        } else {
            asm volatile("cp.async.wait_group 0;" ::: "memory");
        }
        __syncthreads();
        compute(t & 1);
        __syncthreads();
    }

    // ---- epilogue
#pragma unroll
    for (int mt = 0; mt < 2; mt++) {
        const int mr = m0 + wm * 32 + mt * 16 + (lane >> 2);
#pragma unroll
        for (int nt = 0; nt < 8; nt++) {
            const int nc = n0 + wn * 64 + nt * 8 + (lane & 3) * 2;
            float v0 = acc[mt][nt][0], v1 = acc[mt][nt][1];
            float v2 = acc[mt][nt][2], v3 = acc[mt][nt][3];
            if (SPLITK) {
                if (nc < N) {
                    atomicAdd(&C[(size_t)mr * ldc + nc], v0);
                    atomicAdd(&C[(size_t)mr * ldc + nc + 1], v1);
                    atomicAdd(&C[(size_t)(mr + 8) * ldc + nc], v2);
                    atomicAdd(&C[(size_t)(mr + 8) * ldc + nc + 1], v3);
                }
                continue;
            }
            if (EPI >= 1) {
                const float b0 = bias[nc], b1 = bias[nc + 1];
                v0 += b0; v1 += b1; v2 += b0; v3 += b1;
            }
            if (WSPLIT) {
                bf16 h0, l0, h1, l1, h2, l2, h3, l3;
                bsplit(v0, h0, l0); bsplit(v1, h1, l1);
                bsplit(v2, h2, l2); bsplit(v3, h3, l3);
                __nv_bfloat162 ha = {h0, h1}, hb = {h2, h3};
                __nv_bfloat162 la = {l0, l1}, lb = {l2, l3};
                *reinterpret_cast<uint32_t*>(&Chi[(size_t)mr * ldc + nc])       = *(uint32_t*)&ha;
                *reinterpret_cast<uint32_t*>(&Chi[(size_t)(mr + 8) * ldc + nc]) = *(uint32_t*)&hb;
                *reinterpret_cast<uint32_t*>(&Clo[(size_t)mr * ldc + nc])       = *(uint32_t*)&la;
                *reinterpret_cast<uint32_t*>(&Clo[(size_t)(mr + 8) * ldc + nc]) = *(uint32_t*)&lb;
            } else {
                *reinterpret_cast<float2*>(&C[(size_t)mr * ldc + nc])       = make_float2(v0, v1);
                *reinterpret_cast<float2*>(&C[(size_t)(mr + 8) * ldc + nc]) = make_float2(v2, v3);
            }
        }
    }
}

// ---------------- split helper + mega prep ----------------
__device__ __forceinline__ void split4(const float* in, bf16* hi, bf16* lo, int i) {
    float4 v = reinterpret_cast<const float4*>(in)[i];
    bf16 h0, l0, h1, l1, h2, l2, h3, l3;
    bsplit(v.x, h0, l0); bsplit(v.y, h1, l1);
    bsplit(v.z, h2, l2); bsplit(v.w, h3, l3);
    __nv_bfloat162 hA = {h0, h1}, hB = {h2, h3};
    __nv_bfloat162 lA = {l0, l1}, lB = {l2, l3};
    uint2 hu = {*(uint32_t*)&hA, *(uint32_t*)&hB};
    uint2 lu = {*(uint32_t*)&lA, *(uint32_t*)&lB};
    reinterpret_cast<uint2*>(hi)[i] = hu;
    reinterpret_cast<uint2*>(lo)[i] = lu;
}

// segments: x 1024 | w_inp 512 | in_proj 4096 | x_proj 192 | xdb-zero 192 | out-bias 1024
__global__ void __launch_bounds__(256)
prep_kernel(const float* __restrict__ x, const float* __restrict__ w_inp,
            const float* __restrict__ in_proj, const float* __restrict__ x_proj,
            const float* __restrict__ b_outp,
            bf16* xH, bf16* xL, bf16* wiH, bf16* wiL, bf16* ipH, bf16* ipL,
            bf16* w4H, bf16* w4L, float* __restrict__ xdb, float* __restrict__ out)
{
    const int blk = blockIdx.x;
    const int tid = threadIdx.x;
    if (blk < 1024) {
        split4(x, xH, xL, blk * 256 + tid);
    } else if (blk < 1536) {
        split4(w_inp, wiH, wiL, (blk - 1024) * 256 + tid);
    } else if (blk < 5632) {
        split4(in_proj, ipH, ipL, (blk - 1536) * 256 + tid);
    } else if (blk < 5824) {
        split4(x_proj, w4H, w4L, (blk - 5632) * 256 + tid);
    } else if (blk < 6016) {
        reinterpret_cast<float4*>(xdb)[(blk - 5824) * 256 + tid] =
            make_float4(0.f, 0.f, 0.f, 0.f);
    } else {   // out[m][n] = b_outp[n]  (262144 f4)
        const int i = (blk - 6016) * 256 + tid;
        const int c4 = (i & 127) * 4;
        float4 bv = *reinterpret_cast<const float4*>(&b_outp[c4]);
        reinterpret_cast<float4*>(out)[i] = bv;
    }
}

// ---------------- transpose + split: KxN fp32 -> NxK bf16 hi/lo ----------------
__global__ void __launch_bounds__(256)
tsplit_kernel(const float* __restrict__ in, bf16* __restrict__ hi,
              bf16* __restrict__ lo, int K, int N)
{
    __shared__ float t[32][33];
    const int k0 = blockIdx.y * 32, n0 = blockIdx.x * 32;
    const int tx = threadIdx.x & 31, ty = threadIdx.x >> 5;
#pragma unroll
    for (int j = ty; j < 32; j += 8)
        t[j][tx] = in[(size_t)(k0 + j) * N + n0 + tx];
    __syncthreads();
#pragma unroll
    for (int j = ty; j < 32; j += 8) {
        float v = t[tx][j];
        bf16 h, l; bsplit(v, h, l);
        hi[(size_t)(n0 + j) * K + k0 + tx] = h;
        lo[(size_t)(n0 + j) * K + k0 + tx] = l;
    }
}

// ---------------- bz[n] = sum_j b_inp[j] * in_proj_w[n, j] ----------------
__global__ void __launch_bounds__(256)
bz_kernel(const float* __restrict__ b, const float* __restrict__ W,
          float* __restrict__ bz)
{
    const int w = (blockIdx.x * 256 + threadIdx.x) >> 5;
    const int lane = threadIdx.x & 31;
    if (w >= 2 * D_INNER) return;
    float s = 0.f;
    for (int j = lane; j < D_MODEL; j += 32)
        s += b[j] * W[(size_t)w * D_MODEL + j];
#pragma unroll
    for (int o = 16; o; o >>= 1) s += __shfl_xor_sync(0xFFFFFFFFu, s, o);
    if (lane == 0) bz[w] = s;
}

// ---------------- conv-shift + silu: xc ONLY ----------------
__global__ void __launch_bounds__(256)
conv_kernel(const float* __restrict__ rnn, const float* __restrict__ xz,
            const float* __restrict__ conv_w, const float* __restrict__ conv_b,
            float* __restrict__ xc, bf16* __restrict__ xch, bf16* __restrict__ xcl)
{
    const size_t idx = (size_t)blockIdx.x * 256 + threadIdx.x;
    const int b = (int)(idx / D_INNER);
    const int d = (int)(idx % D_INNER);
    const size_t srow = (size_t)b * (D_INNER * STATE_W) + (size_t)d * STATE_W;

    float4 cs = *reinterpret_cast<const float4*>(rnn + srow);
    float xi = xz[(size_t)b * (2 * D_INNER) + d];
    float4 w = *reinterpret_cast<const float4*>(conv_w + d * 4);

    float v = cs.y * w.x + cs.z * w.y + cs.w * w.z + xi * w.w + conv_b[d];
    float s = siluf(v);
    xc[idx] = s;
    bf16 h, l; bsplit(s, h, l);
    xch[idx] = h; xcl[idx] = l;
}

// ======================================================================
// state_kernel: fused dt-dot (fp32) + conv-state shift + SSM + y gating.
// grid (D_INNER/256, BATCH/16). block 256 = one d each, 16 batches.
// smem: w5 tile [256][64] (+pad) staged once, xdb rows [16][96].
// ======================================================================
#define ST_BQ    16
#define ST_SMEM  ((256 * 65 + ST_BQ * 96) * 4)   // 72704 B

__global__ void __launch_bounds__(256, 1)
state_kernel(const float* __restrict__ rnn, const float* __restrict__ xz,
             const float* __restrict__ xdb, const float* __restrict__ w5,
             const float* __restrict__ dtb, const float* __restrict__ xc_,
             const float* __restrict__ A_log, const float* __restrict__ Dp,
             float* __restrict__ ost, bf16* __restrict__ yh, bf16* __restrict__ yl)
{
    extern __shared__ float sm[];
    float* w5s  = sm;                 // [256][65]
    float* xdbs = sm + 256 * 65;      // [16][96]

    const int tid = threadIdx.x;
    const int d0  = blockIdx.x * 256;
    const int b0  = blockIdx.y * ST_BQ;
    const int d   = d0 + tid;

    // stage w5 rows for this d-chunk: w5[d0+row][0..63]
#pragma unroll
    for (int it = 0; it < 16; it++) {
        const int i = it * 256 + tid;           // 0..4095 f4 units
        const int row = i >> 4, c4 = (i & 15) * 4;
        float4 v = *reinterpret_cast<const float4*>(&w5[(size_t)(d0 + row) * DT_RANK + c4]);
        w5s[row * 65 + c4 + 0] = v.x;
        w5s[row * 65 + c4 + 1] = v.y;
        w5s[row * 65 + c4 + 2] = v.z;
        w5s[row * 65 + c4 + 3] = v.w;
    }
    // stage xdb rows b0..b0+15 (96 floats each = 384 f4)
#pragma unroll
    for (int it = 0; it < 2; it++) {
        const int i = it * 256 + tid;
        if (i < ST_BQ * 24) {
            const int row = i / 24, c4 = (i % 24) * 4;
            float4 v = *reinterpret_cast<const float4*>(&xdb[(size_t)(b0 + row) * XDB_COLS + c4]);
            *reinterpret_cast<float4*>(&xdbs[row * 96 + c4]) = v;
        }
    }
    __syncthreads();

    // per-thread constants
    const float dtbd = dtb[d];
    const float Dd   = Dp[d];
    float eA[D_STATE];
#pragma unroll
    for (int q = 0; q < 4; q++) {
        float4 a = *reinterpret_cast<const float4*>(&A_log[(size_t)d * D_STATE + q * 4]);
        eA[q * 4 + 0] = __expf(a.x);
        eA[q * 4 + 1] = __expf(a.y);
        eA[q * 4 + 2] = __expf(a.z);
        eA[q * 4 + 3] = __expf(a.w);
    }
    const float* w5r = &w5s[tid * 65];

#pragma unroll 1
    for (int bb = 0; bb < ST_BQ; bb++) {
        const int b = b0 + bb;
        const float* xr = &xdbs[bb * 96];
        // dt = softplus(dot(xdb[b,0:64], w5[d,:]) + dtb[d])
        float dt = dtbd;
#pragma unroll
        for (int k = 0; k < DT_RANK; k++) dt += xr[k] * w5r[k];
        dt = softplusf(dt);

        const size_t bd = (size_t)b * D_INNER + d;
        const float xc = xc_[bd];
        const float xi = xz[(size_t)b * (2 * D_INNER) + d];
        const float z  = xz[(size_t)b * (2 * D_INNER) + D_INNER + d];
        const float dtxc = dt * xc;

        const size_t srow = (size_t)b * (D_INNER * STATE_W) + (size_t)d * STATE_W;
        const float4* rr = reinterpret_cast<const float4*>(rnn + srow);
        float4* wr = reinterpret_cast<float4*>(ost + srow);

        float4 cs = rr[0];
        wr[0] = make_float4(cs.y, cs.z, cs.w, xi);

        float y = 0.f;
#pragma unroll
        for (int q = 0; q < 4; q++) {
            float4 s = rr[q + 1];
            float sn[4] = {s.x, s.y, s.z, s.w};
            float on[4];
#pragma unroll
            for (int i = 0; i < 4; i++) {
                const int n = q * 4 + i;
                const float sv = sn[i] * __expf(-dt * eA[n]) + dtxc * xr[DT_RANK + n];
                on[i] = sv;
                y += sv * xr[DT_RANK + D_STATE + n];
            }
            wr[q + 1] = make_float4(on[0], on[1], on[2], on[3]);
        }
        y = (y + Dd * xc) * siluf(z);
        bf16 h, l; bsplit(y, h, l);
        yh[bd] = h; yl[bd] = l;
    }
}

// ---------------- launch ----------------
#define GETP(sym, var) float* var; cudaGetSymbolAddress((void**)&var, sym)
#define GETB(sym, var) bf16* var; cudaGetSymbolAddress((void**)&var, sym)

extern "C" void kernel_launch(void* const* d_in, const int* in_sizes, int n_in,
                              void* d_out, int out_size)
{
    const float* x          = (const float*)d_in[0];
    const float* rnn        = (const float*)d_in[1];
    const float* w_inp      = (const float*)d_in[2];
    const float* b_inp      = (const float*)d_in[3];
    const float* w_outp     = (const float*)d_in[4];
    const float* b_outp     = (const float*)d_in[5];
    const float* in_proj_w  = (const float*)d_in[6];
    const float* conv_w     = (const float*)d_in[7];
    const float* conv_b     = (const float*)d_in[8];
    const float* x_proj_w   = (const float*)d_in[9];
    const float* dt_proj_w  = (const float*)d_in[10];
    const float* dt_proj_b  = (const float*)d_in[11];
    const float* A_log      = (const float*)d_in[12];
    const float* Dp         = (const float*)d_in[13];
    const float* out_proj_w = (const float*)d_in[14];

    float* out = (float*)d_out;
    float* out_states = out + (size_t)BATCH * OUT_SIZE;

    GETP(g_xz, p_xz);   GETP(g_xc, p_xc);   GETP(g_xdb, p_xdb);  GETP(g_bz, p_bz);
    GETB(g_x_hi, xH);   GETB(g_x_lo, xL);
    GETB(g_xc_hi, xcH); GETB(g_xc_lo, xcL);
    GETB(g_y_hi, yH);   GETB(g_y_lo, yL);
    GETB(g_wi_hi, wiH); GETB(g_wi_lo, wiL);
    GETB(g_ip_hi, ipH); GETB(g_ip_lo, ipL);
    GETB(g_wxz_hi, wxH); GETB(g_wxz_lo, wxL);
    GETB(g_w4_hi, w4H); GETB(g_w4_lo, w4L);
    GETB(g_opT_hi, opH); GETB(g_opT_lo, opL);
    GETB(g_woT_hi, woH); GETB(g_woT_lo, woL);
    GETB(g_wf_hi, wfH); GETB(g_wf_lo, wfL);

    cudaFuncSetAttribute(bgemm<0, false, true >, cudaFuncAttributeMaxDynamicSharedMemorySize, TG_SMEM);
    cudaFuncSetAttribute(bgemm<1, false, false>, cudaFuncAttributeMaxDynamicSharedMemorySize, TG_SMEM);
    cudaFuncSetAttribute(bgemm<0, true,  false>, cudaFuncAttributeMaxDynamicSharedMemorySize, TG_SMEM);
    cudaFuncSetAttribute(state_kernel, cudaFuncAttributeMaxDynamicSharedMemorySize, ST_SMEM);

    dim3 blk(256);

    // 1) mega prep (splits + xdb zero + out bias-init)
    prep_kernel<<<7040, blk>>>(x, w_inp, in_proj_w, x_proj_w, b_outp,
                               xH, xL, wiH, wiL, ipH, ipL, w4H, w4L, p_xdb, out);
    // 2,3) transpose splits
    tsplit_kernel<<<dim3(D_INNER / 32, D_MODEL / 32), blk>>>(out_proj_w, opH, opL, D_MODEL, D_INNER);
    tsplit_kernel<<<dim3(OUT_SIZE / 32, D_MODEL / 32), blk>>>(w_outp, woH, woL, D_MODEL, OUT_SIZE);
    // 4) bz = b_inp @ in_proj_w^T
    bz_kernel<<<(2 * D_INNER * 32 + 255) / 256, blk>>>(b_inp, in_proj_w, p_bz);
    // 5) W12 = in_proj @ w_inp^T -> [4096 x 512] split
    bgemm<0, false, true><<<dim3(IN_SIZE / 128, 2 * D_INNER / 128), blk, TG_SMEM>>>(
        ipH, ipL, wiH, wiL, nullptr, wxH, wxL, nullptr,
        2 * D_INNER, IN_SIZE, D_MODEL, D_MODEL, D_MODEL, IN_SIZE);
    // 6) Wf = w_outp^T @ out_proj -> [512 x 2048] split
    bgemm<0, false, true><<<dim3(D_INNER / 128, OUT_SIZE / 128), blk, TG_SMEM>>>(
        woH, woL, opH, opL, nullptr, wfH, wfL, nullptr,
        OUT_SIZE, D_INNER, D_MODEL, D_MODEL, D_MODEL, D_INNER);
    // 7) xz = x @ W12^T + bz  (2048x4096, K=512)
    bgemm<1, false, false><<<dim3(2 * D_INNER / 128, BATCH / 128), blk, TG_SMEM>>>(
        xH, xL, wxH, wxL, p_xz, nullptr, nullptr, p_bz,
        BATCH, 2 * D_INNER, IN_SIZE, IN_SIZE, IN_SIZE, 2 * D_INNER);
    // 8) conv -> xc
    conv_kernel<<<(BATCH * D_INNER) / 256, blk>>>(rnn, p_xz, conv_w, conv_b, p_xc, xcH, xcL);
    // 9) xdb = xc @ x_proj^T (split-K=8, atomics)
    bgemm<0, true, false><<<dim3(1, BATCH / 128, 8), blk, TG_SMEM>>>(
        xcH, xcL, w4H, w4L, p_xdb, nullptr, nullptr, nullptr,
        BATCH, XDB_COLS, D_INNER, D_INNER, D_INNER, XDB_COLS);
    // 10) fused dt + state update + y (coalesced 80B rows)
    state_kernel<<<dim3(D_INNER / 256, BATCH / ST_BQ), blk, ST_SMEM>>>(
        rnn, p_xz, p_xdb, dt_proj_w, dt_proj_b, p_xc, A_log, Dp,
        out_states, yH, yL);
    // 11) out += y @ Wf^T  (split-K=2, out pre-initialized to bias)
    bgemm<0, true, false><<<dim3(OUT_SIZE / 128, BATCH / 128, 2), blk, TG_SMEM>>>(
        yH, yL, wfH, wfL, out, nullptr, nullptr, nullptr,
        BATCH, OUT_SIZE, D_INNER, D_INNER, D_INNER, OUT_SIZE);
}